// round 7
// baseline (speedup 1.0000x reference)
#include <cuda_runtime.h>
#include <stdint.h>
#include <math.h>

#define POINCARE_BOUND 0.99999f
typedef unsigned long long u64;

// ---------------------------------------------------------------------------
// constant-memory weights + biases (warp-uniform -> constant port, LDC.128)
// ---------------------------------------------------------------------------
__constant__ __align__(16) float cWc1[32 * 64];
__constant__ __align__(16) float cWc2[32 * 64];
__constant__ __align__(16) float cW0 [64 * 64];
__constant__ __align__(16) float cW1 [64 * 32];
__constant__ __align__(16) float cbc [64];
__constant__ __align__(16) float cb0 [64];
__constant__ __align__(16) float cb1 [32];

// ---------------------------------------------------------------------------
// packed f32x2 primitives
// ---------------------------------------------------------------------------
__device__ __forceinline__ u64 pk2(float lo, float hi) {
    u64 r; asm("mov.b64 %0, {%1, %2};" : "=l"(r) : "f"(lo), "f"(hi)); return r;
}
__device__ __forceinline__ void upk2(u64 v, float& lo, float& hi) {
    asm("mov.b64 {%0, %1}, %2;" : "=f"(lo), "=f"(hi) : "l"(v));
}
__device__ __forceinline__ u64 fma2(u64 a, u64 b, u64 c) {
    u64 d; asm("fma.rn.f32x2 %0, %1, %2, %3;" : "=l"(d) : "l"(a), "l"(b), "l"(c)); return d;
}

// ---------------------------------------------------------------------------
// fast scalar math (MUFU approx; operand norms are O(1) here)
// ---------------------------------------------------------------------------
__device__ __forceinline__ float rcpf(float x)  { float r; asm("rcp.approx.f32 %0, %1;"  : "=f"(r) : "f"(x)); return r; }
__device__ __forceinline__ float sqrtfa(float x){ float r; asm("sqrt.approx.f32 %0, %1;" : "=f"(r) : "f"(x)); return r; }
__device__ __forceinline__ float lg2fa(float x) { float r; asm("lg2.approx.f32 %0, %1;"  : "=f"(r) : "f"(x)); return r; }
__device__ __forceinline__ float ex2fa(float x) { float r; asm("ex2.approx.f32 %0, %1;"  : "=f"(r) : "f"(x)); return r; }

__device__ __forceinline__ float log_scale(float ss) {    // atanh(min(n,B))/n
    float n = fmaxf(sqrtfa(ss), 1e-15f);
    float m = fminf(n, POINCARE_BOUND);
    float r = (1.f + m) * rcpf(1.f - m);
    return (0.34657359f * lg2fa(r)) * rcpf(n);
}
__device__ __forceinline__ float exp_scale(float ss) {     // tanh(n)/n
    float n = fmaxf(sqrtfa(ss), 1e-15f);
    float e = ex2fa(n * -2.8853901f);
    return ((1.f - e) * rcpf(1.f + e)) * rcpf(n);
}
// mobius coefficients from scalar dots: out = a*x + b*y
__device__ __forceinline__ void mobius_coef(float x2, float y2, float xy, float& a, float& b) {
    float inv = rcpf(fmaxf(1.f + 2.f * xy + x2 * y2, 1e-15f));
    a = (1.f + 2.f * xy + y2) * inv;
    b = (1.f - x2) * inv;
}

// ---------------------------------------------------------------------------
// dual-row matvec: o = v @ W for rows A and B sharing each weight load.
// Outputs go to per-thread smem columns (sm[idx*128]); epilogue accumulates
// ss = |raw|^2 and d = raw . dv  (dv in constant memory).
// ---------------------------------------------------------------------------
template<int IN, int OUT, int CH>
__device__ __forceinline__ void mm2_smem(const u64* vA, const u64* vB, const float* W,
                                         const float* dv, u64* smA, u64* smB,
                                         float& ssA, float& ssB, float& dA, float& dB)
{
    ssA = 0.f; ssB = 0.f; dA = 0.f; dB = 0.f;
#pragma unroll
    for (int c0 = 0; c0 < OUT; c0 += CH) {
        u64 aA[CH / 2], aB[CH / 2];
#pragma unroll
        for (int j = 0; j < CH / 2; ++j) { aA[j] = 0ull; aB[j] = 0ull; }
#pragma unroll
        for (int k2 = 0; k2 < IN / 2; ++k2) {
            float a0, a1, b0, b1;
            upk2(vA[k2], a0, a1); upk2(vB[k2], b0, b1);
            const u64 va0 = pk2(a0, a0), va1 = pk2(a1, a1);
            const u64 vb0 = pk2(b0, b0), vb1 = pk2(b1, b1);
            const ulonglong2* w0 = reinterpret_cast<const ulonglong2*>(W + (2 * k2)     * OUT + c0);
            const ulonglong2* w1 = reinterpret_cast<const ulonglong2*>(W + (2 * k2 + 1) * OUT + c0);
#pragma unroll
            for (int j = 0; j < CH / 4; ++j) {
                ulonglong2 wa = w0[j], wb = w1[j];
                aA[2*j]   = fma2(va0, wa.x, aA[2*j]);   aA[2*j+1] = fma2(va0, wa.y, aA[2*j+1]);
                aA[2*j]   = fma2(va1, wb.x, aA[2*j]);   aA[2*j+1] = fma2(va1, wb.y, aA[2*j+1]);
                aB[2*j]   = fma2(vb0, wa.x, aB[2*j]);   aB[2*j+1] = fma2(vb0, wa.y, aB[2*j+1]);
                aB[2*j]   = fma2(vb1, wb.x, aB[2*j]);   aB[2*j+1] = fma2(vb1, wb.y, aB[2*j+1]);
            }
        }
#pragma unroll
        for (int j = 0; j < CH / 2; ++j) {
            float f0, f1, g0, g1;
            upk2(aA[j], f0, f1); upk2(aB[j], g0, g1);
            float w0 = dv[c0 + 2*j], w1 = dv[c0 + 2*j + 1];
            ssA = fmaf(f0, f0, fmaf(f1, f1, ssA));
            ssB = fmaf(g0, g0, fmaf(g1, g1, ssB));
            dA  = fmaf(f0, w0, fmaf(f1, w1, dA));
            dB  = fmaf(g0, w0, fmaf(g1, w1, dB));
            smA[(c0 / 2 + j) * 128] = aA[j];
            smB[(c0 / 2 + j) * 128] = aB[j];
        }
    }
}

// dual-row matvec with outputs kept in registers (for the narrow branches)
template<int IN, int OUT, int CH>
__device__ __forceinline__ void mm2_reg(const u64* vA, const u64* vB, const float* W,
                                        const float* dv, u64* oA, u64* oB,
                                        float& ssA, float& ssB, float& dA, float& dB)
{
    ssA = 0.f; ssB = 0.f; dA = 0.f; dB = 0.f;
#pragma unroll
    for (int c0 = 0; c0 < OUT; c0 += CH) {
        u64 aA[CH / 2], aB[CH / 2];
#pragma unroll
        for (int j = 0; j < CH / 2; ++j) { aA[j] = 0ull; aB[j] = 0ull; }
#pragma unroll
        for (int k2 = 0; k2 < IN / 2; ++k2) {
            float a0, a1, b0, b1;
            upk2(vA[k2], a0, a1); upk2(vB[k2], b0, b1);
            const u64 va0 = pk2(a0, a0), va1 = pk2(a1, a1);
            const u64 vb0 = pk2(b0, b0), vb1 = pk2(b1, b1);
            const ulonglong2* w0 = reinterpret_cast<const ulonglong2*>(W + (2 * k2)     * OUT + c0);
            const ulonglong2* w1 = reinterpret_cast<const ulonglong2*>(W + (2 * k2 + 1) * OUT + c0);
#pragma unroll
            for (int j = 0; j < CH / 4; ++j) {
                ulonglong2 wa = w0[j], wb = w1[j];
                aA[2*j]   = fma2(va0, wa.x, aA[2*j]);   aA[2*j+1] = fma2(va0, wa.y, aA[2*j+1]);
                aA[2*j]   = fma2(va1, wb.x, aA[2*j]);   aA[2*j+1] = fma2(va1, wb.y, aA[2*j+1]);
                aB[2*j]   = fma2(vb0, wa.x, aB[2*j]);   aB[2*j+1] = fma2(vb0, wa.y, aB[2*j+1]);
                aB[2*j]   = fma2(vb1, wb.x, aB[2*j]);   aB[2*j+1] = fma2(vb1, wb.y, aB[2*j+1]);
            }
        }
#pragma unroll
        for (int j = 0; j < CH / 2; ++j) {
            float f0, f1, g0, g1;
            upk2(aA[j], f0, f1); upk2(aB[j], g0, g1);
            float w0 = dv[c0 + 2*j], w1 = dv[c0 + 2*j + 1];
            ssA = fmaf(f0, f0, fmaf(f1, f1, ssA));
            ssB = fmaf(g0, g0, fmaf(g1, g1, ssB));
            dA  = fmaf(f0, w0, fmaf(f1, w1, dA));
            dB  = fmaf(g0, w0, fmaf(g1, w1, dB));
            oA[c0 / 2 + j] = aA[j];
            oB[c0 / 2 + j] = aB[j];
        }
    }
}

// load 32-wide row, pack, apply logmap0
__device__ __forceinline__ void load_log32p(const float* __restrict__ gx, int row, u64* v2) {
    const float4* xp = reinterpret_cast<const float4*>(gx + (size_t)row * 32);
    float ss = 0.f;
#pragma unroll
    for (int i = 0; i < 8; ++i) {
        float4 v = xp[i];
        v2[2*i]   = pk2(v.x, v.y);
        v2[2*i+1] = pk2(v.z, v.w);
        ss = fmaf(v.x, v.x, ss); ss = fmaf(v.y, v.y, ss);
        ss = fmaf(v.z, v.z, ss); ss = fmaf(v.w, v.w, ss);
    }
    float s = log_scale(ss);
    const u64 s2 = pk2(s, s);
#pragma unroll
    for (int i = 0; i < 16; ++i) {
        float lo, hi; upk2(v2[i], lo, hi);
        v2[i] = pk2(lo * s, hi * s);
    }
}

// ---------------------------------------------------------------------------
// kernel: 128 threads, 2 rows/thread (rows t and t+128 of a 256-row block).
// Per-thread smem columns hold raw matvec outputs; mobius/exp/log chains are
// folded into scalar dot bookkeeping + one linear-combination pass.
// ---------------------------------------------------------------------------
__global__ void __launch_bounds__(128, 2)
poincare_mlp_kernel(const float* __restrict__ gx1,
                    const float* __restrict__ gx2,
                    float* __restrict__ gout,
                    int N)
{
    extern __shared__ u64 sm[];   // buffer0: 2 rows x 32 u64 x 128 thr (raw1/raw3)
                                  // buffer1: 2 rows x 16 u64 x 128 thr (raw4)
    const int tid = threadIdx.x;
    u64* smA = sm + tid;                       // row A, 64-wide buffer
    u64* smB = sm + 32 * 128 + tid;            // row B
    u64* smA4 = sm + 64 * 128 + tid;           // row A, 32-wide buffer
    u64* smB4 = sm + 64 * 128 + 16 * 128 + tid;

    int r0 = blockIdx.x * 256 + tid;
    int r1 = r0 + 128;
    r0 = r0 < N ? r0 : N - 1;
    r1 = r1 < N ? r1 : N - 1;

    // bias self-dots (cheap, warp-uniform LDC)
    float bc2 = 0.f, b0sq = 0.f, b1sq = 0.f;
#pragma unroll
    for (int i = 0; i < 64; ++i) bc2  = fmaf(cbc[i], cbc[i], bc2);
#pragma unroll
    for (int i = 0; i < 64; ++i) b0sq = fmaf(cb0[i], cb0[i], b0sq);
#pragma unroll
    for (int i = 0; i < 32; ++i) b1sq = fmaf(cb1[i], cb1[i], b1sq);

    // ---- branch 1: raw1 = logmap0(x1) @ Wc1 -> smem ----
    float ss1A, ss1B, d1cA, d1cB;
    {
        u64 vA[16], vB[16];
        load_log32p(gx1, r0, vA);
        load_log32p(gx1, r1, vB);
        mm2_smem<32, 64, 16>(vA, vB, cWc1, cbc, smA, smB, ss1A, ss1B, d1cA, d1cB);
    }

    // ---- branch 2: raw2 = logmap0(x2) @ Wc2 -> regs ----
    float ss2A, ss2B, d2cA, d2cB;
    u64 rw2A[32], rw2B[32];
    {
        u64 vA[16], vB[16];
        load_log32p(gx2, r0, vA);
        load_log32p(gx2, r1, vB);
        mm2_reg<32, 64, 16>(vA, vB, cWc2, cbc, rw2A, rw2B, ss2A, ss2B, d2cA, d2cB);
    }

    // ---- dot12 = raw1 . raw2 ----
    float d12A = 0.f, d12B = 0.f;
#pragma unroll
    for (int j = 0; j < 32; ++j) {
        float a0, a1, b0, b1;
        upk2(smA[j * 128], a0, a1); upk2(rw2A[j], b0, b1);
        d12A = fmaf(a0, b0, fmaf(a1, b1, d12A));
        upk2(smB[j * 128], a0, a1); upk2(rw2B[j], b0, b1);
        d12B = fmaf(a0, b0, fmaf(a1, b1, d12B));
    }

    // ---- scalar chain: expmap both, mobius(h1,h2), mobius(.,bc), logmap ----
    // produces v = fa*raw1 + fb*raw2 + fc*bc
    float faA, fbA, fcA, faB, fbB, fcB;
    {
        float s1 = exp_scale(ss1A), s2 = exp_scale(ss2A);
        float a, b; mobius_coef(s1*s1*ss1A, s2*s2*ss2A, s1*s2*d12A, a, b);
        float p = a * s1, q = b * s2;
        float m2  = p*p*ss1A + q*q*ss2A + 2.f*p*q*d12A;
        float mbc = p*d1cA + q*d2cA;
        float a2, b2; mobius_coef(m2, bc2, mbc, a2, b2);
        float al = a2 * p, be = a2 * q, gc = b2;
        float g2 = al*al*ss1A + be*be*ss2A + gc*gc*bc2
                 + 2.f*(al*be*d12A + al*gc*d1cA + be*gc*d2cA);
        float sL = log_scale(g2);
        faA = sL * al; fbA = sL * be; fcA = sL * gc;
    }
    {
        float s1 = exp_scale(ss1B), s2 = exp_scale(ss2B);
        float a, b; mobius_coef(s1*s1*ss1B, s2*s2*ss2B, s1*s2*d12B, a, b);
        float p = a * s1, q = b * s2;
        float m2  = p*p*ss1B + q*q*ss2B + 2.f*p*q*d12B;
        float mbc = p*d1cB + q*d2cB;
        float a2, b2; mobius_coef(m2, bc2, mbc, a2, b2);
        float al = a2 * p, be = a2 * q, gc = b2;
        float g2 = al*al*ss1B + be*be*ss2B + gc*gc*bc2
                 + 2.f*(al*be*d12B + al*gc*d1cB + be*gc*d2cB);
        float sL = log_scale(g2);
        faB = sL * al; fbB = sL * be; fcB = sL * gc;
    }

    // ---- combine into layer-0 input (in place over rw2 registers) ----
#pragma unroll
    for (int j = 0; j < 32; ++j) {
        float a0, a1, b0, b1;
        upk2(smA[j * 128], a0, a1); upk2(rw2A[j], b0, b1);
        float c0 = cbc[2*j], c1 = cbc[2*j+1];
        rw2A[j] = pk2(fmaf(faA, a0, fmaf(fbA, b0, fcA * c0)),
                      fmaf(faA, a1, fmaf(fbA, b1, fcA * c1)));
        upk2(smB[j * 128], a0, a1); upk2(rw2B[j], b0, b1);
        rw2B[j] = pk2(fmaf(faB, a0, fmaf(fbB, b0, fcB * c0)),
                      fmaf(faB, a1, fmaf(fbB, b1, fcB * c1)));
    }

    // ---- layer 0: raw3 = v @ W0 -> smem (reuse buffer) ----
    float ss3A, ss3B, d3A, d3B;
    mm2_smem<64, 64, 16>(rw2A, rw2B, cW0, cb0, smA, smB, ss3A, ss3B, d3A, d3B);

    // scalar chain: expmap, mobius(.,b0), logmap -> v2 = fg*raw3 + fd*b0
    float fgA, fdA, fgB, fdB;
    {
        float s3 = exp_scale(ss3A);
        float a, b; mobius_coef(s3*s3*ss3A, b0sq, s3*d3A, a, b);
        float ga = a * s3, de = b;
        float g2 = ga*ga*ss3A + de*de*b0sq + 2.f*ga*de*d3A;
        float sL = log_scale(g2);
        fgA = sL * ga; fdA = sL * de;
    }
    {
        float s3 = exp_scale(ss3B);
        float a, b; mobius_coef(s3*s3*ss3B, b0sq, s3*d3B, a, b);
        float ga = a * s3, de = b;
        float g2 = ga*ga*ss3B + de*de*b0sq + 2.f*ga*de*d3B;
        float sL = log_scale(g2);
        fgB = sL * ga; fdB = sL * de;
    }

    // combine into layer-1 input
#pragma unroll
    for (int j = 0; j < 32; ++j) {
        float a0, a1;
        float c0 = cb0[2*j], c1 = cb0[2*j+1];
        upk2(smA[j * 128], a0, a1);
        rw2A[j] = pk2(fmaf(fgA, a0, fdA * c0), fmaf(fgA, a1, fdA * c1));
        upk2(smB[j * 128], a0, a1);
        rw2B[j] = pk2(fmaf(fgB, a0, fdB * c0), fmaf(fgB, a1, fdB * c1));
    }

    // ---- layer 1: raw4 = v2 @ W1 -> smem ----
    float ss4A, ss4B, d4A, d4B;
    mm2_smem<64, 32, 16>(rw2A, rw2B, cW1, cb1, smA4, smB4, ss4A, ss4B, d4A, d4B);

    // scalar chain: expmap, mobius(.,b1) -> out = pa*raw4 + pb*b1
    float paA, pbA, paB, pbB;
    {
        float s4 = exp_scale(ss4A);
        float a, b; mobius_coef(s4*s4*ss4A, b1sq, s4*d4A, a, b);
        paA = a * s4; pbA = b;
    }
    {
        float s4 = exp_scale(ss4B);
        float a, b; mobius_coef(s4*s4*ss4B, b1sq, s4*d4B, a, b);
        paB = a * s4; pbB = b;
    }

    // ---- final combine + store ----
    float4* opA = reinterpret_cast<float4*>(gout + (size_t)r0 * 32);
    float4* opB = reinterpret_cast<float4*>(gout + (size_t)r1 * 32);
#pragma unroll
    for (int q = 0; q < 8; ++q) {
        float a0, a1, a2, a3;
        float c0 = cb1[4*q], c1 = cb1[4*q+1], c2 = cb1[4*q+2], c3 = cb1[4*q+3];
        upk2(smA4[(2*q) * 128], a0, a1); upk2(smA4[(2*q+1) * 128], a2, a3);
        opA[q] = make_float4(fmaf(paA, a0, pbA * c0), fmaf(paA, a1, pbA * c1),
                             fmaf(paA, a2, pbA * c2), fmaf(paA, a3, pbA * c3));
        upk2(smB4[(2*q) * 128], a0, a1); upk2(smB4[(2*q+1) * 128], a2, a3);
        opB[q] = make_float4(fmaf(paB, a0, pbB * c0), fmaf(paB, a1, pbB * c1),
                             fmaf(paB, a2, pbB * c2), fmaf(paB, a3, pbB * c3));
    }
}

// ---------------------------------------------------------------------------
// launch
// ---------------------------------------------------------------------------
extern "C" void kernel_launch(void* const* d_in, const int* in_sizes, int n_in,
                              void* d_out, int out_size)
{
    const float* x1 = (const float*)d_in[0];
    const float* x2 = (const float*)d_in[1];

    cudaMemcpyToSymbolAsync(cWc1, d_in[2], 32 * 64 * sizeof(float), 0, cudaMemcpyDeviceToDevice);
    cudaMemcpyToSymbolAsync(cWc2, d_in[3], 32 * 64 * sizeof(float), 0, cudaMemcpyDeviceToDevice);
    cudaMemcpyToSymbolAsync(cbc,  d_in[4], 64 * sizeof(float),      0, cudaMemcpyDeviceToDevice);
    cudaMemcpyToSymbolAsync(cW0,  d_in[5], 64 * 64 * sizeof(float), 0, cudaMemcpyDeviceToDevice);
    cudaMemcpyToSymbolAsync(cb0,  d_in[6], 64 * sizeof(float),      0, cudaMemcpyDeviceToDevice);
    cudaMemcpyToSymbolAsync(cW1,  d_in[7], 64 * 32 * sizeof(float), 0, cudaMemcpyDeviceToDevice);
    cudaMemcpyToSymbolAsync(cb1,  d_in[8], 32 * sizeof(float),      0, cudaMemcpyDeviceToDevice);

    // smem: (2*32 + 2*16) u64-slots * 128 threads = 96*128*8 = 98304 bytes
    const int smem_bytes = 96 * 128 * 8;
    cudaFuncSetAttribute(poincare_mlp_kernel,
                         cudaFuncAttributeMaxDynamicSharedMemorySize, smem_bytes);

    float* out = (float*)d_out;
    const int N = in_sizes[0] / 32;
    const int blocks = (N + 255) / 256;
    poincare_mlp_kernel<<<blocks, 128, smem_bytes>>>(x1, x2, out, N);
}

// round 8
// speedup vs baseline: 1.0953x; 1.0953x over previous
#include <cuda_runtime.h>
#include <stdint.h>
#include <math.h>

#define POINCARE_BOUND 0.99999f
typedef unsigned long long u64;

// ---------------------------------------------------------------------------
// constant memory: branch weights + all biases (warp-uniform -> LDC port).
// W0/W1 go to shared memory (LDS port) to split traffic across ports.
// ---------------------------------------------------------------------------
__constant__ __align__(16) float cWc1[32 * 64];
__constant__ __align__(16) float cWc2[32 * 64];
__constant__ __align__(16) float cbc [64];
__constant__ __align__(16) float cb0 [64];
__constant__ __align__(16) float cb1 [32];

// ---------------------------------------------------------------------------
// packed f32x2 primitives
// ---------------------------------------------------------------------------
__device__ __forceinline__ u64 pk2(float lo, float hi) {
    u64 r; asm("mov.b64 %0, {%1, %2};" : "=l"(r) : "f"(lo), "f"(hi)); return r;
}
__device__ __forceinline__ void upk2(u64 v, float& lo, float& hi) {
    asm("mov.b64 {%0, %1}, %2;" : "=f"(lo), "=f"(hi) : "l"(v));
}
__device__ __forceinline__ u64 fma2(u64 a, u64 b, u64 c) {
    u64 d; asm("fma.rn.f32x2 %0, %1, %2, %3;" : "=l"(d) : "l"(a), "l"(b), "l"(c)); return d;
}
__device__ __forceinline__ u64 mul2(u64 a, u64 b) {
    u64 d; asm("mul.rn.f32x2 %0, %1, %2;" : "=l"(d) : "l"(a), "l"(b)); return d;
}
__device__ __forceinline__ float hsum2(u64 v) {
    float lo, hi; upk2(v, lo, hi); return lo + hi;
}

__device__ __forceinline__ uint32_t smem_u32(const void* p) {
    uint32_t a;
    asm("{ .reg .u64 t; cvta.to.shared.u64 t, %1; cvt.u32.u64 %0, t; }" : "=r"(a) : "l"(p));
    return a;
}
// guaranteed LDS.128: 16 bytes from shared at 32-bit address (imm-foldable)
__device__ __forceinline__ void lds128(uint32_t addr, u64& a, u64& b) {
    asm volatile("ld.shared.v2.b64 {%0, %1}, [%2];" : "=l"(a), "=l"(b) : "r"(addr));
}

// ---------------------------------------------------------------------------
// fast scalar math (MUFU approx; operand norms are O(1) here)
// ---------------------------------------------------------------------------
__device__ __forceinline__ float rcpf(float x)  { float r; asm("rcp.approx.f32 %0, %1;"  : "=f"(r) : "f"(x)); return r; }
__device__ __forceinline__ float sqrtfa(float x){ float r; asm("sqrt.approx.f32 %0, %1;" : "=f"(r) : "f"(x)); return r; }
__device__ __forceinline__ float lg2fa(float x) { float r; asm("lg2.approx.f32 %0, %1;"  : "=f"(r) : "f"(x)); return r; }
__device__ __forceinline__ float ex2fa(float x) { float r; asm("ex2.approx.f32 %0, %1;"  : "=f"(r) : "f"(x)); return r; }

__device__ __forceinline__ float log_scale(float ss) {    // atanh(min(n,B))/n
    float n = fmaxf(sqrtfa(ss), 1e-15f);
    float m = fminf(n, POINCARE_BOUND);
    float r = (1.f + m) * rcpf(1.f - m);
    return (0.34657359f * lg2fa(r)) * rcpf(n);
}
__device__ __forceinline__ float exp_scale(float ss) {     // tanh(n)/n
    float n = fmaxf(sqrtfa(ss), 1e-15f);
    float e = ex2fa(n * -2.8853901f);
    return ((1.f - e) * rcpf(1.f + e)) * rcpf(n);
}

// ---------------------------------------------------------------------------
// packed vector ops
// ---------------------------------------------------------------------------
template<int D2>
__device__ __forceinline__ float ssum2(const u64* v) {
    u64 a = 0ull;
#pragma unroll
    for (int i = 0; i < D2; ++i) a = fma2(v[i], v[i], a);
    return hsum2(a);
}
template<int D2>
__device__ __forceinline__ void scale2(u64* v, float s) {
    const u64 s2 = pk2(s, s);
#pragma unroll
    for (int i = 0; i < D2; ++i) v[i] = mul2(v[i], s2);
}
template<int D2>
__device__ __forceinline__ void logmap0p(u64* v) { scale2<D2>(v, log_scale(ssum2<D2>(v))); }
template<int D2>
__device__ __forceinline__ void expmap0p(u64* v) { scale2<D2>(v, exp_scale(ssum2<D2>(v))); }

template<int D2>
__device__ __forceinline__ void mobius_addp(u64* x, const u64* y) {
    u64 ax = 0ull, ay = 0ull, axy = 0ull;
#pragma unroll
    for (int i = 0; i < D2; ++i) {
        u64 yi = y[i];
        ax  = fma2(x[i], x[i], ax);
        ay  = fma2(yi,  yi,  ay);
        axy = fma2(x[i], yi, axy);
    }
    float x2 = hsum2(ax), y2 = hsum2(ay), xy = hsum2(axy);
    float a   = 1.f + 2.f * xy + y2;
    float b   = 1.f - x2;
    float inv = rcpf(fmaxf(1.f + 2.f * xy + x2 * y2, 1e-15f));
    const u64 a2 = pk2(a * inv, a * inv);
    const u64 b2 = pk2(b * inv, b * inv);
#pragma unroll
    for (int i = 0; i < D2; ++i)
        x[i] = fma2(b2, y[i], mul2(a2, x[i]));
}

// constant-memory matvec (round-4 form; LDC.128 with immediate addresses)
template<int IN, int OUT, int CH>
__device__ __forceinline__ void matvecC2(const u64* v2, const float* cW, u64* o2) {
#pragma unroll
    for (int c0 = 0; c0 < OUT; c0 += CH) {
        u64 acc[CH / 2];
#pragma unroll
        for (int j = 0; j < CH / 2; ++j) acc[j] = 0ull;
#pragma unroll
        for (int k2 = 0; k2 < IN / 2; ++k2) {
            float lo, hi; upk2(v2[k2], lo, hi);
            const u64 va = pk2(lo, lo), vb = pk2(hi, hi);
            const ulonglong2* w0 = reinterpret_cast<const ulonglong2*>(cW + (2 * k2)     * OUT + c0);
            const ulonglong2* w1 = reinterpret_cast<const ulonglong2*>(cW + (2 * k2 + 1) * OUT + c0);
#pragma unroll
            for (int j = 0; j < CH / 4; ++j) {
                ulonglong2 wa = w0[j];
                acc[2 * j]     = fma2(va, wa.x, acc[2 * j]);
                acc[2 * j + 1] = fma2(va, wa.y, acc[2 * j + 1]);
                ulonglong2 wb = w1[j];
                acc[2 * j]     = fma2(vb, wb.x, acc[2 * j]);
                acc[2 * j + 1] = fma2(vb, wb.y, acc[2 * j + 1]);
            }
        }
#pragma unroll
        for (int j = 0; j < CH / 2; ++j) o2[c0 / 2 + j] = acc[j];
    }
}

// shared-memory matvec: explicit LDS.128, base address + compile-time offsets
template<int IN, int OUT, int CH>
__device__ __forceinline__ void matvecS2(const u64* v2, uint32_t sbase, u64* o2) {
#pragma unroll
    for (int c0 = 0; c0 < OUT; c0 += CH) {
        u64 acc[CH / 2];
#pragma unroll
        for (int j = 0; j < CH / 2; ++j) acc[j] = 0ull;
#pragma unroll
        for (int k2 = 0; k2 < IN / 2; ++k2) {
            float lo, hi; upk2(v2[k2], lo, hi);
            const u64 va = pk2(lo, lo), vb = pk2(hi, hi);
            const uint32_t r0 = sbase + ((2 * k2)     * OUT + c0) * 4;
            const uint32_t r1 = sbase + ((2 * k2 + 1) * OUT + c0) * 4;
#pragma unroll
            for (int j = 0; j < CH / 4; ++j) {
                u64 wa0, wa1, wb0, wb1;
                lds128(r0 + j * 16, wa0, wa1);
                acc[2 * j]     = fma2(va, wa0, acc[2 * j]);
                acc[2 * j + 1] = fma2(va, wa1, acc[2 * j + 1]);
                lds128(r1 + j * 16, wb0, wb1);
                acc[2 * j]     = fma2(vb, wb0, acc[2 * j]);
                acc[2 * j + 1] = fma2(vb, wb1, acc[2 * j + 1]);
            }
        }
#pragma unroll
        for (int j = 0; j < CH / 2; ++j) o2[c0 / 2 + j] = acc[j];
    }
}

// load one 32-wide row, pack, apply logmap0
__device__ __forceinline__ void load_log32p(const float* __restrict__ gx, int row, u64* v2) {
    const float4* xp = reinterpret_cast<const float4*>(gx + (size_t)row * 32);
    u64 a = 0ull;
#pragma unroll
    for (int i = 0; i < 8; ++i) {
        float4 v = xp[i];
        u64 p0 = pk2(v.x, v.y), p1 = pk2(v.z, v.w);
        v2[2 * i] = p0; v2[2 * i + 1] = p1;
        a = fma2(p0, p0, a);
        a = fma2(p1, p1, a);
    }
    scale2<16>(v2, log_scale(hsum2(a)));
}

// ---------------------------------------------------------------------------
// kernel: one thread per row; Wc1/Wc2 on constant port, W0/W1 on LDS port
// ---------------------------------------------------------------------------
__global__ void __launch_bounds__(128, 4)
poincare_mlp_kernel(const float* __restrict__ gx1,
                    const float* __restrict__ gx2,
                    const float* __restrict__ gW0,
                    const float* __restrict__ gW1,
                    float* __restrict__ gout,
                    int N)
{
    __shared__ __align__(16) float sW[64 * 64 + 64 * 32];   // W0 then W1, 24KB

    {   // cooperative fill: 1536 float4, 128 threads -> 12 each
        const float4* g0 = reinterpret_cast<const float4*>(gW0);
        const float4* g1 = reinterpret_cast<const float4*>(gW1);
        float4* s0 = reinterpret_cast<float4*>(sW);
        float4* s1 = reinterpret_cast<float4*>(sW + 64 * 64);
        const int t = threadIdx.x;
#pragma unroll
        for (int i = 0; i < 8; ++i) s0[t + 128 * i] = g0[t + 128 * i];
#pragma unroll
        for (int i = 0; i < 4; ++i) s1[t + 128 * i] = g1[t + 128 * i];
    }
    __syncthreads();
    const uint32_t sb0 = smem_u32(sW);
    const uint32_t sb1 = sb0 + 64 * 64 * 4;

    const int row = blockIdx.x * 128 + threadIdx.x;
    if (row >= N) return;

    u64 u2[16];
    u64 h1[32], h2[32];

    // ---- branch 1: h1 = expmap0(logmap0(x1) @ Wc1)
    load_log32p(gx1, row, u2);
    matvecC2<32, 64, 32>(u2, cWc1, h1);
    expmap0p<32>(h1);

    // ---- branch 2: h2 = expmap0(logmap0(x2) @ Wc2)
    load_log32p(gx2, row, u2);
    matvecC2<32, 64, 32>(u2, cWc2, h2);
    expmap0p<32>(h2);

    // ---- h = mobius_add(mobius_add(h1, h2), bc)
    mobius_addp<32>(h1, h2);
    mobius_addp<32>(h1, reinterpret_cast<const u64*>(cbc));

    // ---- layer 0: mobius_add(expmap0(logmap0(h) @ W0), b0)
    logmap0p<32>(h1);
    matvecS2<64, 64, 32>(h1, sb0, h2);
    expmap0p<32>(h2);
    mobius_addp<32>(h2, reinterpret_cast<const u64*>(cb0));

    // ---- layer 1: mobius_add(expmap0(logmap0(h) @ W1), b1)
    logmap0p<32>(h2);
    u64 o2[16];
    matvecS2<64, 32, 32>(h2, sb1, o2);
    expmap0p<16>(o2);
    mobius_addp<16>(o2, reinterpret_cast<const u64*>(cb1));

    float4* op = reinterpret_cast<float4*>(gout + (size_t)row * 32);
#pragma unroll
    for (int i = 0; i < 8; ++i) {
        float x, y, z, w;
        upk2(o2[2 * i],     x, y);
        upk2(o2[2 * i + 1], z, w);
        op[i] = make_float4(x, y, z, w);
    }
}

// ---------------------------------------------------------------------------
// launch
// ---------------------------------------------------------------------------
extern "C" void kernel_launch(void* const* d_in, const int* in_sizes, int n_in,
                              void* d_out, int out_size)
{
    const float* x1 = (const float*)d_in[0];
    const float* x2 = (const float*)d_in[1];
    const float* W0 = (const float*)d_in[5];
    const float* W1 = (const float*)d_in[7];

    cudaMemcpyToSymbolAsync(cWc1, d_in[2], 32 * 64 * sizeof(float), 0, cudaMemcpyDeviceToDevice);
    cudaMemcpyToSymbolAsync(cWc2, d_in[3], 32 * 64 * sizeof(float), 0, cudaMemcpyDeviceToDevice);
    cudaMemcpyToSymbolAsync(cbc,  d_in[4], 64 * sizeof(float),      0, cudaMemcpyDeviceToDevice);
    cudaMemcpyToSymbolAsync(cb0,  d_in[6], 64 * sizeof(float),      0, cudaMemcpyDeviceToDevice);
    cudaMemcpyToSymbolAsync(cb1,  d_in[8], 32 * sizeof(float),      0, cudaMemcpyDeviceToDevice);

    float* out = (float*)d_out;
    const int N = in_sizes[0] / 32;
    const int blocks = (N + 127) / 128;
    poincare_mlp_kernel<<<blocks, 128>>>(x1, x2, W0, W1, out, N);
}

// round 9
// speedup vs baseline: 1.1787x; 1.0762x over previous
#include <cuda_runtime.h>
#include <stdint.h>
#include <math.h>

#define POINCARE_BOUND 0.99999f
typedef unsigned long long u64;

// ---------------------------------------------------------------------------
// Port-balanced weight placement.
//  LDC port (8 cyc/LDC.128): Wc1, Wc2 (full), W0 cols [0:32), W1 cols [0:16)
//  LDS crossbar (~16 cyc/LDS.128): W0 cols [32:64), W1 cols [16:32)
//  c = 512+512+512+256 = 1792 -> 14336 cyc ; s = 512+256 = 768 -> 12288 cyc
// ---------------------------------------------------------------------------
__constant__ __align__(16) float cWc1[32 * 64];
__constant__ __align__(16) float cWc2[32 * 64];
__constant__ __align__(16) float cW0 [64 * 64];   // full copy; only cols [0:32) read
__constant__ __align__(16) float cW1 [64 * 32];   // full copy; only cols [0:16) read
__constant__ __align__(16) float cbc [64];
__constant__ __align__(16) float cb0 [64];
__constant__ __align__(16) float cb1 [32];

// ---------------------------------------------------------------------------
// packed f32x2 primitives
// ---------------------------------------------------------------------------
__device__ __forceinline__ u64 pk2(float lo, float hi) {
    u64 r; asm("mov.b64 %0, {%1, %2};" : "=l"(r) : "f"(lo), "f"(hi)); return r;
}
__device__ __forceinline__ void upk2(u64 v, float& lo, float& hi) {
    asm("mov.b64 {%0, %1}, %2;" : "=f"(lo), "=f"(hi) : "l"(v));
}
__device__ __forceinline__ u64 fma2(u64 a, u64 b, u64 c) {
    u64 d; asm("fma.rn.f32x2 %0, %1, %2, %3;" : "=l"(d) : "l"(a), "l"(b), "l"(c)); return d;
}
__device__ __forceinline__ u64 mul2(u64 a, u64 b) {
    u64 d; asm("mul.rn.f32x2 %0, %1, %2;" : "=l"(d) : "l"(a), "l"(b)); return d;
}
__device__ __forceinline__ float hsum2(u64 v) {
    float lo, hi; upk2(v, lo, hi); return lo + hi;
}
__device__ __forceinline__ uint32_t smem_u32(const void* p) {
    uint32_t a;
    asm("{ .reg .u64 t; cvta.to.shared.u64 t, %1; cvt.u32.u64 %0, t; }" : "=r"(a) : "l"(p));
    return a;
}
__device__ __forceinline__ void lds128(uint32_t addr, u64& a, u64& b) {
    asm volatile("ld.shared.v2.b64 {%0, %1}, [%2];" : "=l"(a), "=l"(b) : "r"(addr));
}

// ---------------------------------------------------------------------------
// fast scalar math (MUFU approx; operand norms are O(1) here)
// ---------------------------------------------------------------------------
__device__ __forceinline__ float rcpf(float x)  { float r; asm("rcp.approx.f32 %0, %1;"  : "=f"(r) : "f"(x)); return r; }
__device__ __forceinline__ float sqrtfa(float x){ float r; asm("sqrt.approx.f32 %0, %1;" : "=f"(r) : "f"(x)); return r; }
__device__ __forceinline__ float lg2fa(float x) { float r; asm("lg2.approx.f32 %0, %1;"  : "=f"(r) : "f"(x)); return r; }
__device__ __forceinline__ float ex2fa(float x) { float r; asm("ex2.approx.f32 %0, %1;"  : "=f"(r) : "f"(x)); return r; }

__device__ __forceinline__ float log_scale(float ss) {    // atanh(min(n,B))/n
    float n = fmaxf(sqrtfa(ss), 1e-15f);
    float m = fminf(n, POINCARE_BOUND);
    float r = (1.f + m) * rcpf(1.f - m);
    return (0.34657359f * lg2fa(r)) * rcpf(n);
}
__device__ __forceinline__ float exp_scale(float ss) {     // tanh(n)/n
    float n = fmaxf(sqrtfa(ss), 1e-15f);
    float e = ex2fa(n * -2.8853901f);
    return ((1.f - e) * rcpf(1.f + e)) * rcpf(n);
}

// ---------------------------------------------------------------------------
// packed vector ops
// ---------------------------------------------------------------------------
template<int D2>
__device__ __forceinline__ float ssum2(const u64* v) {
    u64 a = 0ull;
#pragma unroll
    for (int i = 0; i < D2; ++i) a = fma2(v[i], v[i], a);
    return hsum2(a);
}
template<int D2>
__device__ __forceinline__ void scale2(u64* v, float s) {
    const u64 s2 = pk2(s, s);
#pragma unroll
    for (int i = 0; i < D2; ++i) v[i] = mul2(v[i], s2);
}
template<int D2>
__device__ __forceinline__ void logmap0p(u64* v) { scale2<D2>(v, log_scale(ssum2<D2>(v))); }
template<int D2>
__device__ __forceinline__ void expmap0p(u64* v) { scale2<D2>(v, exp_scale(ssum2<D2>(v))); }

template<int D2>
__device__ __forceinline__ void mobius_addp(u64* x, const u64* y) {
    u64 ax = 0ull, ay = 0ull, axy = 0ull;
#pragma unroll
    for (int i = 0; i < D2; ++i) {
        u64 yi = y[i];
        ax  = fma2(x[i], x[i], ax);
        ay  = fma2(yi,  yi,  ay);
        axy = fma2(x[i], yi, axy);
    }
    float x2 = hsum2(ax), y2 = hsum2(ay), xy = hsum2(axy);
    float a   = 1.f + 2.f * xy + y2;
    float b   = 1.f - x2;
    float inv = rcpf(fmaxf(1.f + 2.f * xy + x2 * y2, 1e-15f));
    const u64 a2 = pk2(a * inv, a * inv);
    const u64 b2 = pk2(b * inv, b * inv);
#pragma unroll
    for (int i = 0; i < D2; ++i)
        x[i] = fma2(b2, y[i], mul2(a2, x[i]));
}

// constant-port matvec over columns [C0, C0+COLS) of W[IN][OUT]
template<int IN, int OUT, int C0, int COLS, int CH>
__device__ __forceinline__ void mvC(const u64* v2, const float* cW, u64* o2) {
#pragma unroll
    for (int c0 = C0; c0 < C0 + COLS; c0 += CH) {
        u64 acc[CH / 2];
#pragma unroll
        for (int j = 0; j < CH / 2; ++j) acc[j] = 0ull;
#pragma unroll
        for (int k2 = 0; k2 < IN / 2; ++k2) {
            float lo, hi; upk2(v2[k2], lo, hi);
            const u64 va = pk2(lo, lo), vb = pk2(hi, hi);
            const ulonglong2* w0 = reinterpret_cast<const ulonglong2*>(cW + (2 * k2)     * OUT + c0);
            const ulonglong2* w1 = reinterpret_cast<const ulonglong2*>(cW + (2 * k2 + 1) * OUT + c0);
#pragma unroll
            for (int j = 0; j < CH / 4; ++j) {
                ulonglong2 wa = w0[j];
                acc[2 * j]     = fma2(va, wa.x, acc[2 * j]);
                acc[2 * j + 1] = fma2(va, wa.y, acc[2 * j + 1]);
                ulonglong2 wb = w1[j];
                acc[2 * j]     = fma2(vb, wb.x, acc[2 * j]);
                acc[2 * j + 1] = fma2(vb, wb.y, acc[2 * j + 1]);
            }
        }
#pragma unroll
        for (int j = 0; j < CH / 2; ++j) o2[(c0 - C0) / 2 + j] = acc[j];
    }
}

// shared-port matvec over columns [C0, C0+COLS); smem holds the SAME layout
// as the gmem matrix (row stride OUT floats); sbase points at the matrix.
template<int IN, int OUT, int C0, int COLS, int CH>
__device__ __forceinline__ void mvS(const u64* v2, uint32_t sbase, u64* o2) {
#pragma unroll
    for (int c0 = C0; c0 < C0 + COLS; c0 += CH) {
        u64 acc[CH / 2];
#pragma unroll
        for (int j = 0; j < CH / 2; ++j) acc[j] = 0ull;
#pragma unroll
        for (int k2 = 0; k2 < IN / 2; ++k2) {
            float lo, hi; upk2(v2[k2], lo, hi);
            const u64 va = pk2(lo, lo), vb = pk2(hi, hi);
            const uint32_t r0 = sbase + ((2 * k2)     * OUT + c0) * 4;
            const uint32_t r1 = sbase + ((2 * k2 + 1) * OUT + c0) * 4;
#pragma unroll
            for (int j = 0; j < CH / 4; ++j) {
                u64 wa0, wa1, wb0, wb1;
                lds128(r0 + j * 16, wa0, wa1);
                acc[2 * j]     = fma2(va, wa0, acc[2 * j]);
                acc[2 * j + 1] = fma2(va, wa1, acc[2 * j + 1]);
                lds128(r1 + j * 16, wb0, wb1);
                acc[2 * j]     = fma2(vb, wb0, acc[2 * j]);
                acc[2 * j + 1] = fma2(vb, wb1, acc[2 * j + 1]);
            }
        }
#pragma unroll
        for (int j = 0; j < CH / 2; ++j) o2[(c0 - C0) / 2 + j] = acc[j];
    }
}

// load one 32-wide row, pack, apply logmap0
__device__ __forceinline__ void load_log32p(const float* __restrict__ gx, int row, u64* v2) {
    const float4* xp = reinterpret_cast<const float4*>(gx + (size_t)row * 32);
    u64 a = 0ull;
#pragma unroll
    for (int i = 0; i < 8; ++i) {
        float4 v = xp[i];
        u64 p0 = pk2(v.x, v.y), p1 = pk2(v.z, v.w);
        v2[2 * i] = p0; v2[2 * i + 1] = p1;
        a = fma2(p0, p0, a);
        a = fma2(p1, p1, a);
    }
    scale2<16>(v2, log_scale(hsum2(a)));
}

// ---------------------------------------------------------------------------
// kernel: one thread per row; each of W0/W1 split column-wise across LDC+LDS
// ---------------------------------------------------------------------------
__global__ void __launch_bounds__(128, 4)
poincare_mlp_kernel(const float* __restrict__ gx1,
                    const float* __restrict__ gx2,
                    const float* __restrict__ gW0,
                    const float* __restrict__ gW1,
                    float* __restrict__ gout,
                    int N)
{
    __shared__ __align__(16) float sW[64 * 64 + 64 * 32];   // W0 then W1 (full copies)

    {
        const float4* g0 = reinterpret_cast<const float4*>(gW0);
        const float4* g1 = reinterpret_cast<const float4*>(gW1);
        float4* s0 = reinterpret_cast<float4*>(sW);
        float4* s1 = reinterpret_cast<float4*>(sW + 64 * 64);
        const int t = threadIdx.x;
#pragma unroll
        for (int i = 0; i < 8; ++i) s0[t + 128 * i] = g0[t + 128 * i];
#pragma unroll
        for (int i = 0; i < 4; ++i) s1[t + 128 * i] = g1[t + 128 * i];
    }
    __syncthreads();
    const uint32_t sb0 = smem_u32(sW);
    const uint32_t sb1 = sb0 + 64 * 64 * 4;

    const int row = blockIdx.x * 128 + threadIdx.x;
    if (row >= N) return;

    u64 u2[16];
    u64 h1[32], h2[32];

    // ---- branch 1: h1 = expmap0(logmap0(x1) @ Wc1)       [LDC]
    load_log32p(gx1, row, u2);
    mvC<32, 64, 0, 64, 32>(u2, cWc1, h1);
    expmap0p<32>(h1);

    // ---- branch 2: h2 = expmap0(logmap0(x2) @ Wc2)       [LDC]
    load_log32p(gx2, row, u2);
    mvC<32, 64, 0, 64, 32>(u2, cWc2, h2);
    expmap0p<32>(h2);

    // ---- h = mobius_add(mobius_add(h1, h2), bc)
    mobius_addp<32>(h1, h2);
    mobius_addp<32>(h1, reinterpret_cast<const u64*>(cbc));

    // ---- layer 0: cols [0:32) via LDC, cols [32:64) via LDS
    logmap0p<32>(h1);
    mvC<64, 64, 0,  32, 32>(h1, cW0, h2);        // outputs 0..31  -> h2[0..15]
    mvS<64, 64, 32, 32, 32>(h1, sb0, h2 + 16);   // outputs 32..63 -> h2[16..31]
    expmap0p<32>(h2);
    mobius_addp<32>(h2, reinterpret_cast<const u64*>(cb0));

    // ---- layer 1: cols [0:16) via LDC, cols [16:32) via LDS
    logmap0p<32>(h2);
    u64 o2[16];
    mvC<64, 32, 0,  16, 16>(h2, cW1, o2);        // outputs 0..15  -> o2[0..7]
    mvS<64, 32, 16, 16, 16>(h2, sb1, o2 + 8);    // outputs 16..31 -> o2[8..15]
    expmap0p<16>(o2);
    mobius_addp<16>(o2, reinterpret_cast<const u64*>(cb1));

    float4* op = reinterpret_cast<float4*>(gout + (size_t)row * 32);
#pragma unroll
    for (int i = 0; i < 8; ++i) {
        float x, y, z, w;
        upk2(o2[2 * i],     x, y);
        upk2(o2[2 * i + 1], z, w);
        op[i] = make_float4(x, y, z, w);
    }
}

// ---------------------------------------------------------------------------
// launch
// ---------------------------------------------------------------------------
extern "C" void kernel_launch(void* const* d_in, const int* in_sizes, int n_in,
                              void* d_out, int out_size)
{
    const float* x1 = (const float*)d_in[0];
    const float* x2 = (const float*)d_in[1];
    const float* W0 = (const float*)d_in[5];
    const float* W1 = (const float*)d_in[7];

    cudaMemcpyToSymbolAsync(cWc1, d_in[2], 32 * 64 * sizeof(float), 0, cudaMemcpyDeviceToDevice);
    cudaMemcpyToSymbolAsync(cWc2, d_in[3], 32 * 64 * sizeof(float), 0, cudaMemcpyDeviceToDevice);
    cudaMemcpyToSymbolAsync(cbc,  d_in[4], 64 * sizeof(float),      0, cudaMemcpyDeviceToDevice);
    cudaMemcpyToSymbolAsync(cW0,  d_in[5], 64 * 64 * sizeof(float), 0, cudaMemcpyDeviceToDevice);
    cudaMemcpyToSymbolAsync(cb0,  d_in[6], 64 * sizeof(float),      0, cudaMemcpyDeviceToDevice);
    cudaMemcpyToSymbolAsync(cW1,  d_in[7], 64 * 32 * sizeof(float), 0, cudaMemcpyDeviceToDevice);
    cudaMemcpyToSymbolAsync(cb1,  d_in[8], 32 * sizeof(float),      0, cudaMemcpyDeviceToDevice);

    float* out = (float*)d_out;
    const int N = in_sizes[0] / 32;
    const int blocks = (N + 127) / 128;
    poincare_mlp_kernel<<<blocks, 128>>>(x1, x2, W0, W1, out, N);
}